// round 7
// baseline (speedup 1.0000x reference)
#include <cuda_runtime.h>
#include <cuda_bf16.h>
#include <cstdint>

#define BATCH 2
#define NANCH 261888
#define PRE_NMS 6000
#define PRE2 1536          // prefix length for fast-path NMS
#define NW2 (PRE2 / 64)    // 24 words per prefix row
#define PROP 1000
#define NMS_THR 0.7f
#define NBINS 2048
#define SCAP 12288
#define BUCKET_CAP 2048
#define SB_GRID 128        // sortbox cutbin-relative grid width

#define HS_BLOCKS 64
#define HS_THREADS 1024
#define HS_PER_THREAD 4    // float4s per thread: 64*1024*4 = 262144 >= 261888

typedef unsigned long long u64;

// ---------------- scratch (zero at module load; re-zeroed by tail kernel) -------
__device__ int g_hist[BATCH * NBINS];
__device__ int g_offset[BATCH * NBINS];
__device__ int g_binfill[BATCH * NBINS];
__device__ int g_cutbin[BATCH];
__device__ unsigned int g_ticket;
__device__ int g_ready;
__device__ u64 g_sorted[BATCH * SCAP];
__device__ float4 g_boxes[BATCH * PRE_NMS];
__device__ u64 g_mask2[BATCH * PRE2 * NW2];   // 576 KB prefix mask

// ---------------- helpers ----------------
__device__ __forceinline__ int score_bin(float s) {
    int b = (int)(s * (float)NBINS);
    if (b < 0) b = 0;
    if (b > NBINS - 1) b = NBINS - 1;
    return b;
}

// keep ⟺ iou > THR ⟺ (1+THR)*inter > THR*(areaR+areaC+eps)  (denominator > 0)
__device__ __forceinline__ bool iou_gt(float4 a, float aR7, float4 c, float cA7) {
    float ih = fmaxf(fminf(a.z, c.z) - fmaxf(a.x, c.x), 0.f);
    float iw = fmaxf(fminf(a.w, c.w) - fmaxf(a.y, c.y), 0.f);
    float inter = ih * iw;
    return 1.7f * inter > aR7 + cA7;
}

// ------ 1: fused histogram + suffix-scan + scatter (single read of cls) --------
__global__ void __launch_bounds__(HS_THREADS, 1)
histscatter_kernel(const float4* __restrict__ cls4) {
    __shared__ int h[BATCH * NBINS];   // 16 KB
    for (int t = threadIdx.x; t < BATCH * NBINS; t += HS_THREADS) h[t] = 0;
    __syncthreads();
    const int total4 = BATCH * NANCH / 2;   // 261888
    const int half = NANCH / 2;
    const int gsz = HS_BLOCKS * HS_THREADS; // 65536
    int tid = blockIdx.x * HS_THREADS + threadIdx.x;

    // phase A: histogram; cache scores in registers
    float sc[HS_PER_THREAD * 2];
#pragma unroll
    for (int u = 0; u < HS_PER_THREAD; ++u) {
        int t = tid + u * gsz;
        float y = -1.f, w = -1.f;
        if (t < total4) {
            float4 v = cls4[t];
            y = v.y; w = v.w;
            int b = t / half;
            atomicAdd(&h[b * NBINS + score_bin(y)], 1);
            atomicAdd(&h[b * NBINS + score_bin(w)], 1);
        }
        sc[u * 2 + 0] = y;
        sc[u * 2 + 1] = w;
    }
    __syncthreads();
    for (int t = threadIdx.x; t < BATCH * NBINS; t += HS_THREADS)
        if (h[t]) atomicAdd(&g_hist[t], h[t]);

    __threadfence();
    __shared__ int is_last;
    if (threadIdx.x == 0)
        is_last = (atomicAdd(&g_ticket, 1u) == HS_BLOCKS - 1) ? 1 : 0;
    __syncthreads();

    if (is_last) {
        // suffix scan: 1024 threads, 2 bins each
        __shared__ int sA[1024], sB[1024];
        for (int b = 0; b < BATCH; ++b) {
            int t = threadIdx.x;
            int base = b * NBINS + t * 2;
            int h0 = g_hist[base + 0], h1 = g_hist[base + 1];
            int sum = h0 + h1;
            sA[t] = sum;
            __syncthreads();
            int* src = sA; int* dst = sB;
            for (int d = 1; d < 1024; d <<= 1) {
                int v = src[t];
                if (t + d < 1024) v += src[t + d];
                dst[t] = v;
                __syncthreads();
                int* tmp = src; src = dst; dst = tmp;
            }
            int excl = src[t] - sum;
            int off1 = excl;
            int off0 = off1 + h1;
            g_offset[base + 0] = off0; g_offset[base + 1] = off1;
            if (off1 + h1 >= PRE_NMS) atomicMax(&g_cutbin[b], t * 2 + 1);
            else if (off0 + h0 >= PRE_NMS) atomicMax(&g_cutbin[b], t * 2 + 0);
            __syncthreads();
        }
        __threadfence();
        if (threadIdx.x == 0) atomicExch(&g_ready, 1);
    }

    // all blocks wait for the scan results (all blocks are co-resident: 64 <= #SMs)
    if (threadIdx.x == 0) {
        while (atomicAdd(&g_ready, 0) == 0) __nanosleep(128);
    }
    __syncthreads();
    __threadfence();

    // phase B: scatter from register-cached scores (no re-read of cls)
    int cut0 = g_cutbin[0];
    int cut1 = g_cutbin[1];
#pragma unroll
    for (int u = 0; u < HS_PER_THREAD; ++u) {
        int t = tid + u * gsz;
        if (t >= total4) continue;
        int b = t / half;
        int i0 = (t - b * half) * 2;
        int cut = (b == 0) ? cut0 : cut1;
#pragma unroll
        for (int e = 0; e < 2; ++e) {
            float s = sc[u * 2 + e];
            int i = i0 + e;
            int q = score_bin(s);
            if (q >= cut) {
                int pos = g_offset[b * NBINS + q] + atomicAdd(&g_binfill[b * NBINS + q], 1);
                if (pos < SCAP) {
                    unsigned int sb = __float_as_uint(s);
                    g_sorted[b * SCAP + pos] =
                        ((u64)sb << 32) | (u64)(0xFFFFFFFFu - (unsigned)i);
                }
            }
        }
    }
}

// ---------------- 2: per-bucket sort + box decode (cutbin-relative grid) -------
__global__ void sortbox_kernel(const float* __restrict__ rpn_bbox,
                               const float* __restrict__ anchors) {
    int b = blockIdx.y;
    int cut = g_cutbin[b];
    __shared__ u64 s[BUCKET_CAP];
    for (int bin = cut + blockIdx.x; bin < NBINS; bin += SB_GRID) {
        int cnt = g_hist[b * NBINS + bin];
        if (cnt <= 0) continue;
        if (cnt > BUCKET_CAP) cnt = BUCKET_CAP;
        int off = g_offset[b * NBINS + bin];
        if (off >= PRE_NMS) continue;
        int P = 1;
        while (P < cnt) P <<= 1;
        const u64* src = g_sorted + (size_t)b * SCAP + off;
        for (int t = threadIdx.x; t < P; t += blockDim.x)
            s[t] = (t < cnt) ? src[t] : 0ULL;
        __syncthreads();
        if (cnt > 1) {
            for (int k = 2; k <= P; k <<= 1) {
                for (int j = k >> 1; j > 0; j >>= 1) {
                    for (int i = threadIdx.x; i < P; i += blockDim.x) {
                        int ixj = i ^ j;
                        if (ixj > i) {
                            bool dir = ((i & k) == 0);
                            u64 a = s[i], c = s[ixj];
                            if ((a < c) == dir) { s[i] = c; s[ixj] = a; }
                        }
                    }
                    __syncthreads();
                }
            }
        }
        for (int t = threadIdx.x; t < cnt; t += blockDim.x) {
            int rank = off + t;
            if (rank >= PRE_NMS) continue;
            unsigned int low = (unsigned int)(s[t] & 0xFFFFFFFFu);
            int idx = (int)(0xFFFFFFFFu - low);
            size_t base = ((size_t)b * NANCH + (size_t)idx) * 4;
            float a0 = anchors[base + 0], a1 = anchors[base + 1];
            float a2 = anchors[base + 2], a3 = anchors[base + 3];
            float d0 = rpn_bbox[base + 0] * 0.1f;
            float d1 = rpn_bbox[base + 1] * 0.1f;
            float d2 = rpn_bbox[base + 2] * 0.2f;
            float d3 = rpn_bbox[base + 3] * 0.2f;
            float h = a2 - a0, w = a3 - a1;
            float cy = a0 + 0.5f * h + d0 * h;
            float cx = a1 + 0.5f * w + d1 * w;
            h = h * expf(d2);
            w = w * expf(d3);
            float y1 = cy - 0.5f * h;
            float x1 = cx - 0.5f * w;
            float y2 = y1 + h;
            float x2 = x1 + w;
            y1 = fminf(fmaxf(y1, 0.f), 1.f);
            x1 = fminf(fmaxf(x1, 0.f), 1.f);
            y2 = fminf(fmaxf(y2, 0.f), 1.f);
            x2 = fminf(fmaxf(x2, 0.f), 1.f);
            g_boxes[b * PRE_NMS + rank] = make_float4(y1, x1, y2, x2);
        }
        __syncthreads();
    }
}

// ---------------- 3: prefix IoU bitmask (upper triangle, no division) ----------
__global__ void __launch_bounds__(128) maskpre_kernel() {
    int b = blockIdx.z;
    int row0 = blockIdx.y * 128;
    int col0 = blockIdx.x * 64;
    if (col0 + 63 <= row0) return;   // sub-diagonal: never read
    __shared__ float4 cbox[64];
    __shared__ float cA7[64];
    int t = threadIdx.x;             // 128 threads
    if (t < 64) {
        float4 cb = g_boxes[b * PRE_NMS + col0 + t];
        cbox[t] = cb;
        cA7[t] = 0.7f * ((cb.z - cb.x) * (cb.w - cb.y) + 1e-8f);
    }
    __syncthreads();
    int r = row0 + t;
    float4 rb = g_boxes[b * PRE_NMS + r];
    float aR7 = 0.7f * ((rb.z - rb.x) * (rb.w - rb.y));
    unsigned lo = 0, hi = 0;
#pragma unroll
    for (int jj = 0; jj < 32; ++jj)
        if (iou_gt(rb, aR7, cbox[jj], cA7[jj])) lo |= (1u << jj);
#pragma unroll
    for (int jj = 0; jj < 32; ++jj)
        if (iou_gt(rb, aR7, cbox[32 + jj], cA7[32 + jj])) hi |= (1u << jj);
    g_mask2[(b * PRE2 + r) * NW2 + blockIdx.x] = ((u64)hi << 32) | lo;
}

// ---------------- 4: NMS (prefix fast path + direct fallback) + cleanup --------
__global__ void nms_kernel(float* __restrict__ out) {
    if (blockIdx.x >= BATCH) {
        // cleanup blocks: re-zero scratch for the next graph replay
        int start = (blockIdx.x - BATCH) * blockDim.x + threadIdx.x;
        for (int t = start; t < BATCH * NBINS; t += 8 * blockDim.x) {
            g_hist[t] = 0;
            g_binfill[t] = 0;
        }
        if (start == 0) {
            g_cutbin[0] = 0; g_cutbin[1] = 0;
            g_ticket = 0u;
            g_ready = 0;
        }
        return;
    }
    int b = blockIdx.x;
    __shared__ int list[PROP];
    __shared__ int s_kc;

    if (threadIdx.x < 32) {
        int lane = threadIdx.x;
        int ll = (lane < NW2) ? lane : 0;
        const u64* M = g_mask2 + (size_t)b * PRE2 * NW2;
        u64 rem = 0;
        u64 cb0[16], cb1[16], cb2[16], cb3[16];
        const int NCH = PRE2 / 16;  // 96 chunks
#pragma unroll
        for (int k = 0; k < 16; ++k) cb0[k] = M[(size_t)(0 * 16 + k) * NW2 + ll];
#pragma unroll
        for (int k = 0; k < 16; ++k) cb1[k] = M[(size_t)(1 * 16 + k) * NW2 + ll];
#pragma unroll
        for (int k = 0; k < 16; ++k) cb2[k] = M[(size_t)(2 * 16 + k) * NW2 + ll];
        int kc = 0;

#define PROCESS_CHUNK(CUR, PFBUF, CHUNK)                                          \
    {                                                                             \
        int chunk = (CHUNK);                                                      \
        int pf = chunk + 3;                                                       \
        if (pf < NCH) {                                                           \
            _Pragma("unroll")                                                     \
            for (int k = 0; k < 16; ++k)                                          \
                PFBUF[k] = M[(size_t)(pf * 16 + k) * NW2 + ll];                   \
        }                                                                         \
        int base = chunk * 16;                                                    \
        int w = base >> 6;                                                        \
        unsigned keptm = 0;                                                       \
        if (lane == w) {                                                          \
            int bp0 = base & 63;                                                  \
            u64 r = rem;                                                          \
            int kcl = kc;                                                         \
            _Pragma("unroll")                                                     \
            for (int k = 0; k < 16; ++k) {                                        \
                if (kcl < PROP && !((r >> (bp0 + k)) & 1ULL)) {                   \
                    keptm |= (1u << k);                                           \
                    r |= CUR[k];                                                  \
                    kcl++;                                                        \
                }                                                                 \
            }                                                                     \
        }                                                                         \
        keptm = __shfl_sync(0xffffffffu, keptm, w);                               \
        _Pragma("unroll")                                                         \
        for (int k = 0; k < 16; ++k)                                              \
            if (keptm & (1u << k)) rem |= CUR[k];                                 \
        if (lane < 16 && ((keptm >> lane) & 1u)) {                                \
            int pos = kc + __popc(keptm & ((1u << lane) - 1u));                   \
            if (pos < PROP) list[pos] = base + lane;                              \
        }                                                                         \
        kc += __popc(keptm);                                                      \
        if (kc >= PROP) goto done;                                                \
    }

        for (int ch = 0; ch < NCH; ch += 4) {
            PROCESS_CHUNK(cb0, cb3, ch + 0)
            PROCESS_CHUNK(cb1, cb0, ch + 1)
            PROCESS_CHUNK(cb2, cb1, ch + 2)
            PROCESS_CHUNK(cb3, cb2, ch + 3)
        }
#undef PROCESS_CHUNK
done:
        if (lane == 0) s_kc = kc;
    }
    __syncthreads();

    int kc = s_kc;
    const float4* bx = g_boxes + b * PRE_NMS;
    float4* o = (float4*)(out + (size_t)b * PROP * 4);
    if (kc >= PROP) {
        for (int r = threadIdx.x; r < PROP; r += blockDim.x) o[r] = bx[list[r]];
        return;
    }

    // fallback: exact direct sequential NMS over all 6000 boxes (rarely taken)
    __shared__ float4 kept[PROP];
    __shared__ float keptA7[PROP];
    int kk = 0;
    for (int i = 0; i < PRE_NMS && kk < PROP; ++i) {
        float4 bi = bx[i];
        float aR7 = 0.7f * ((bi.z - bi.x) * (bi.w - bi.y));
        int sup = 0;
        for (int j = threadIdx.x; j < kk; j += blockDim.x)
            if (iou_gt(bi, aR7, kept[j], keptA7[j])) sup = 1;
        sup = __syncthreads_or(sup);
        if (!sup) {
            if (threadIdx.x == 0) {
                kept[kk] = bi;
                keptA7[kk] = 0.7f * ((bi.z - bi.x) * (bi.w - bi.y) + 1e-8f);
            }
            kk++;
            __syncthreads();
        }
    }
    for (int r = threadIdx.x; r < PROP; r += blockDim.x) {
        float4 v = make_float4(0.f, 0.f, 0.f, 0.f);
        if (r < kk) v = kept[r];
        o[r] = v;
    }
}

// ---------------- launch ----------------
extern "C" void kernel_launch(void* const* d_in, const int* in_sizes, int n_in,
                              void* d_out, int out_size) {
    (void)in_sizes; (void)n_in; (void)out_size;
    const float4* cls4 = (const float4*)d_in[0];
    const float* rpn_bbox = (const float*)d_in[1];
    const float* anchors = (const float*)d_in[2];
    float* out = (float*)d_out;

    histscatter_kernel<<<HS_BLOCKS, HS_THREADS>>>(cls4);
    {
        dim3 grid(SB_GRID, BATCH);
        sortbox_kernel<<<grid, 128>>>(rpn_bbox, anchors);
    }
    {
        dim3 grid(NW2, PRE2 / 128, BATCH);   // (24, 12, 2)
        maskpre_kernel<<<grid, 128>>>();
    }
    nms_kernel<<<BATCH + 8, 256>>>(out);
}

// round 8
// speedup vs baseline: 1.1873x; 1.1873x over previous
#include <cuda_runtime.h>
#include <cuda_bf16.h>
#include <cstdint>

#define BATCH 2
#define NANCH 261888
#define PRE_NMS 6000
#define PRE2 1536          // prefix length for fast-path NMS
#define NW2 (PRE2 / 64)    // 24 words per prefix row
#define PROP 1000
#define NMS_THR 0.7f
#define NBINS 2048
#define SCAP 12288
#define BUCKET_CAP 2048
#define SB_GRID 128        // sortbox cutbin-relative grid width

#define HS_BLOCKS 64
#define HS_THREADS 1024
#define HS_PER_THREAD 4    // float4s per thread: 64*1024*4 = 262144 >= 261888

typedef unsigned long long u64;

// ---------------- scratch (zero at module load; re-zeroed by tail kernel) -------
__device__ int g_hist[BATCH * NBINS];
__device__ int g_offset[BATCH * NBINS];
__device__ int g_binfill[BATCH * NBINS];
__device__ int g_cutbin[BATCH];
__device__ unsigned int g_ticket;
__device__ int g_ready;
__device__ u64 g_sorted[BATCH * SCAP];
__device__ float4 g_boxes[BATCH * PRE_NMS];
__device__ u64 g_mask2[BATCH * PRE2 * NW2];   // 576 KB prefix mask

// ---------------- helpers ----------------
__device__ __forceinline__ int score_bin(float s) {
    int b = (int)(s * (float)NBINS);
    if (b < 0) b = 0;
    if (b > NBINS - 1) b = NBINS - 1;
    return b;
}

// keep ⟺ iou > THR ⟺ (1+THR)*inter > THR*(areaR+areaC+eps)  (denominator > 0)
__device__ __forceinline__ bool iou_gt(float4 a, float aR7, float4 c, float cA7) {
    float ih = fmaxf(fminf(a.z, c.z) - fmaxf(a.x, c.x), 0.f);
    float iw = fmaxf(fminf(a.w, c.w) - fmaxf(a.y, c.y), 0.f);
    float inter = ih * iw;
    return 1.7f * inter > aR7 + cA7;
}

// ------ 1: fused histogram + suffix-scan + scatter (single read of cls) --------
__global__ void __launch_bounds__(HS_THREADS, 1)
histscatter_kernel(const float4* __restrict__ cls4) {
    __shared__ int h[BATCH * NBINS];   // 16 KB
    for (int t = threadIdx.x; t < BATCH * NBINS; t += HS_THREADS) h[t] = 0;
    __syncthreads();
    const int total4 = BATCH * NANCH / 2;   // 261888
    const int half = NANCH / 2;
    const int gsz = HS_BLOCKS * HS_THREADS; // 65536
    int tid = blockIdx.x * HS_THREADS + threadIdx.x;

    // phase A: histogram; cache scores in registers
    float sc[HS_PER_THREAD * 2];
#pragma unroll
    for (int u = 0; u < HS_PER_THREAD; ++u) {
        int t = tid + u * gsz;
        float y = -1.f, w = -1.f;
        if (t < total4) {
            float4 v = cls4[t];
            y = v.y; w = v.w;
            int b = t / half;
            atomicAdd(&h[b * NBINS + score_bin(y)], 1);
            atomicAdd(&h[b * NBINS + score_bin(w)], 1);
        }
        sc[u * 2 + 0] = y;
        sc[u * 2 + 1] = w;
    }
    __syncthreads();
    for (int t = threadIdx.x; t < BATCH * NBINS; t += HS_THREADS)
        if (h[t]) atomicAdd(&g_hist[t], h[t]);

    __threadfence();
    __shared__ int is_last;
    if (threadIdx.x == 0)
        is_last = (atomicAdd(&g_ticket, 1u) == HS_BLOCKS - 1) ? 1 : 0;
    __syncthreads();

    if (is_last) {
        // suffix scan: 1024 threads, 2 bins each
        __shared__ int sA[1024], sB[1024];
        for (int b = 0; b < BATCH; ++b) {
            int t = threadIdx.x;
            int base = b * NBINS + t * 2;
            int h0 = g_hist[base + 0], h1 = g_hist[base + 1];
            int sum = h0 + h1;
            sA[t] = sum;
            __syncthreads();
            int* src = sA; int* dst = sB;
            for (int d = 1; d < 1024; d <<= 1) {
                int v = src[t];
                if (t + d < 1024) v += src[t + d];
                dst[t] = v;
                __syncthreads();
                int* tmp = src; src = dst; dst = tmp;
            }
            int excl = src[t] - sum;
            int off1 = excl;
            int off0 = off1 + h1;
            g_offset[base + 0] = off0; g_offset[base + 1] = off1;
            if (off1 + h1 >= PRE_NMS) atomicMax(&g_cutbin[b], t * 2 + 1);
            else if (off0 + h0 >= PRE_NMS) atomicMax(&g_cutbin[b], t * 2 + 0);
            __syncthreads();
        }
        __threadfence();
        if (threadIdx.x == 0) atomicExch(&g_ready, 1);
    }

    // all blocks wait for the scan results (all blocks are co-resident: 64 <= #SMs)
    if (threadIdx.x == 0) {
        while (atomicAdd(&g_ready, 0) == 0) __nanosleep(128);
    }
    __syncthreads();
    __threadfence();

    // phase B: scatter from register-cached scores (no re-read of cls)
    int cut0 = g_cutbin[0];
    int cut1 = g_cutbin[1];
#pragma unroll
    for (int u = 0; u < HS_PER_THREAD; ++u) {
        int t = tid + u * gsz;
        if (t >= total4) continue;
        int b = t / half;
        int i0 = (t - b * half) * 2;
        int cut = (b == 0) ? cut0 : cut1;
#pragma unroll
        for (int e = 0; e < 2; ++e) {
            float s = sc[u * 2 + e];
            int i = i0 + e;
            int q = score_bin(s);
            if (q >= cut) {
                int pos = g_offset[b * NBINS + q] + atomicAdd(&g_binfill[b * NBINS + q], 1);
                if (pos < SCAP) {
                    unsigned int sb = __float_as_uint(s);
                    g_sorted[b * SCAP + pos] =
                        ((u64)sb << 32) | (u64)(0xFFFFFFFFu - (unsigned)i);
                }
            }
        }
    }
}

// ---------------- 2: per-bucket sort + box decode (cutbin-relative grid) -------
__global__ void sortbox_kernel(const float* __restrict__ rpn_bbox,
                               const float* __restrict__ anchors) {
    int b = blockIdx.y;
    int cut = g_cutbin[b];
    __shared__ u64 s[BUCKET_CAP];
    for (int bin = cut + blockIdx.x; bin < NBINS; bin += SB_GRID) {
        int cnt = g_hist[b * NBINS + bin];
        if (cnt <= 0) continue;
        if (cnt > BUCKET_CAP) cnt = BUCKET_CAP;
        int off = g_offset[b * NBINS + bin];
        if (off >= PRE_NMS) continue;
        int P = 1;
        while (P < cnt) P <<= 1;
        const u64* src = g_sorted + (size_t)b * SCAP + off;
        for (int t = threadIdx.x; t < P; t += blockDim.x)
            s[t] = (t < cnt) ? src[t] : 0ULL;
        __syncthreads();
        if (cnt > 1) {
            for (int k = 2; k <= P; k <<= 1) {
                for (int j = k >> 1; j > 0; j >>= 1) {
                    for (int i = threadIdx.x; i < P; i += blockDim.x) {
                        int ixj = i ^ j;
                        if (ixj > i) {
                            bool dir = ((i & k) == 0);
                            u64 a = s[i], c = s[ixj];
                            if ((a < c) == dir) { s[i] = c; s[ixj] = a; }
                        }
                    }
                    __syncthreads();
                }
            }
        }
        for (int t = threadIdx.x; t < cnt; t += blockDim.x) {
            int rank = off + t;
            if (rank >= PRE_NMS) continue;
            unsigned int low = (unsigned int)(s[t] & 0xFFFFFFFFu);
            int idx = (int)(0xFFFFFFFFu - low);
            size_t base = ((size_t)b * NANCH + (size_t)idx) * 4;
            float a0 = anchors[base + 0], a1 = anchors[base + 1];
            float a2 = anchors[base + 2], a3 = anchors[base + 3];
            float d0 = rpn_bbox[base + 0] * 0.1f;
            float d1 = rpn_bbox[base + 1] * 0.1f;
            float d2 = rpn_bbox[base + 2] * 0.2f;
            float d3 = rpn_bbox[base + 3] * 0.2f;
            float h = a2 - a0, w = a3 - a1;
            float cy = a0 + 0.5f * h + d0 * h;
            float cx = a1 + 0.5f * w + d1 * w;
            h = h * expf(d2);
            w = w * expf(d3);
            float y1 = cy - 0.5f * h;
            float x1 = cx - 0.5f * w;
            float y2 = y1 + h;
            float x2 = x1 + w;
            y1 = fminf(fmaxf(y1, 0.f), 1.f);
            x1 = fminf(fmaxf(x1, 0.f), 1.f);
            y2 = fminf(fmaxf(y2, 0.f), 1.f);
            x2 = fminf(fmaxf(x2, 0.f), 1.f);
            g_boxes[b * PRE_NMS + rank] = make_float4(y1, x1, y2, x2);
        }
        __syncthreads();
    }
}

// ---------------- 3: prefix IoU bitmask (upper triangle, no division) ----------
__global__ void __launch_bounds__(128) maskpre_kernel() {
    int b = blockIdx.z;
    int row0 = blockIdx.y * 128;
    int col0 = blockIdx.x * 64;
    if (col0 + 63 <= row0) return;   // sub-diagonal: never read
    __shared__ float4 cbox[64];
    __shared__ float cA7[64];
    int t = threadIdx.x;             // 128 threads
    if (t < 64) {
        float4 cb = g_boxes[b * PRE_NMS + col0 + t];
        cbox[t] = cb;
        cA7[t] = 0.7f * ((cb.z - cb.x) * (cb.w - cb.y) + 1e-8f);
    }
    __syncthreads();
    int r = row0 + t;
    float4 rb = g_boxes[b * PRE_NMS + r];
    float aR7 = 0.7f * ((rb.z - rb.x) * (rb.w - rb.y));
    unsigned lo = 0, hi = 0;
#pragma unroll
    for (int jj = 0; jj < 32; ++jj)
        if (iou_gt(rb, aR7, cbox[jj], cA7[jj])) lo |= (1u << jj);
#pragma unroll
    for (int jj = 0; jj < 32; ++jj)
        if (iou_gt(rb, aR7, cbox[32 + jj], cA7[32 + jj])) hi |= (1u << jj);
    g_mask2[(b * PRE2 + r) * NW2 + blockIdx.x] = ((u64)hi << 32) | lo;
}

// ---------------- 4: NMS — speculate-then-verify chunks + fallback + cleanup ---
__global__ void nms_kernel(float* __restrict__ out) {
    if (blockIdx.x >= BATCH) {
        // cleanup blocks: re-zero scratch for the next graph replay
        int start = (blockIdx.x - BATCH) * blockDim.x + threadIdx.x;
        for (int t = start; t < BATCH * NBINS; t += 8 * blockDim.x) {
            g_hist[t] = 0;
            g_binfill[t] = 0;
        }
        if (start == 0) {
            g_cutbin[0] = 0; g_cutbin[1] = 0;
            g_ticket = 0u;
            g_ready = 0;
        }
        return;
    }
    int b = blockIdx.x;
    __shared__ int list[PROP];
    __shared__ int s_kc;

    if (threadIdx.x < 32) {
        int lane = threadIdx.x;
        int ll = (lane < NW2) ? lane : 0;
        const u64* M = g_mask2 + (size_t)b * PRE2 * NW2;
        u64 rem = 0;
        u64 cb0[16], cb1[16], cb2[16], cb3[16];
        const int NCH = PRE2 / 16;  // 96 chunks
#pragma unroll
        for (int k = 0; k < 16; ++k) cb0[k] = M[(size_t)(0 * 16 + k) * NW2 + ll];
#pragma unroll
        for (int k = 0; k < 16; ++k) cb1[k] = M[(size_t)(1 * 16 + k) * NW2 + ll];
#pragma unroll
        for (int k = 0; k < 16; ++k) cb2[k] = M[(size_t)(2 * 16 + k) * NW2 + ll];
        int kc = 0;

#define PROCESS_CHUNK(CUR, PFBUF, CHUNK)                                          \
    {                                                                             \
        int chunk = (CHUNK);                                                      \
        int pf = chunk + 3;                                                       \
        if (pf < NCH) {                                                           \
            _Pragma("unroll")                                                     \
            for (int k = 0; k < 16; ++k)                                          \
                PFBUF[k] = M[(size_t)(pf * 16 + k) * NW2 + ll];                   \
        }                                                                         \
        int base = chunk * 16;                                                    \
        int w = base >> 6;                                                        \
        int bp0 = base & 63;                                                      \
        unsigned keptm = 0;                                                       \
        if (lane == w) {                                                          \
            unsigned keptm0 = (~(unsigned)(rem >> bp0)) & 0xFFFFu;                \
            /* diagonal 16x16 block, self-bits cleared, masked by keptm0 */       \
            unsigned dk[16];                                                      \
            _Pragma("unroll")                                                     \
            for (int k = 0; k < 16; ++k)                                          \
                dk[k] = (((unsigned)(CUR[k] >> bp0) & 0xFFFFu) & ~(1u << k))      \
                        & (0u - ((keptm0 >> k) & 1u));                            \
            _Pragma("unroll")                                                     \
            for (int s = 1; s < 16; s <<= 1) {                                    \
                _Pragma("unroll")                                                 \
                for (int k = 0; k < 16; k += 2 * s) dk[k] |= dk[k + s];           \
            }                                                                     \
            if ((dk[0] & keptm0) == 0u) {                                         \
                keptm = keptm0;   /* no in-chunk suppression: speculation exact */\
            } else {                                                              \
                /* rare: exact serial resolution within the chunk */              \
                u64 r = rem;                                                      \
                _Pragma("unroll")                                                 \
                for (int k = 0; k < 16; ++k) {                                    \
                    if (!((r >> (bp0 + k)) & 1ULL)) {                             \
                        keptm |= (1u << k);                                       \
                        r |= CUR[k];                                              \
                    }                                                             \
                }                                                                 \
            }                                                                     \
        }                                                                         \
        keptm = __shfl_sync(0xffffffffu, keptm, w);                               \
        /* trim to first (PROP-kc) kept rows; later rows are discarded anyway */  \
        int pc = __popc(keptm);                                                   \
        int rema = PROP - kc;                                                     \
        if (pc > rema) {                                                          \
            while (pc > rema) {                                                   \
                keptm &= ~(1u << (31 - __clz(keptm)));                            \
                --pc;                                                             \
            }                                                                     \
        }                                                                         \
        /* branch-free masked tree-OR of kept rows into rem (clobbers CUR) */     \
        _Pragma("unroll")                                                         \
        for (int k = 0; k < 16; ++k)                                              \
            CUR[k] &= (u64)(0ULL - (u64)((keptm >> k) & 1u));                     \
        _Pragma("unroll")                                                         \
        for (int s = 1; s < 16; s <<= 1) {                                        \
            _Pragma("unroll")                                                     \
            for (int k = 0; k < 16; k += 2 * s) CUR[k] |= CUR[k + s];             \
        }                                                                         \
        rem |= CUR[0];                                                            \
        if (lane < 16 && ((keptm >> lane) & 1u)) {                                \
            int pos = kc + __popc(keptm & ((1u << lane) - 1u));                   \
            list[pos] = base + lane;                                              \
        }                                                                         \
        kc += pc;                                                                 \
        if (kc >= PROP) goto done;                                                \
    }

        for (int ch = 0; ch < NCH; ch += 4) {
            PROCESS_CHUNK(cb0, cb3, ch + 0)
            PROCESS_CHUNK(cb1, cb0, ch + 1)
            PROCESS_CHUNK(cb2, cb1, ch + 2)
            PROCESS_CHUNK(cb3, cb2, ch + 3)
        }
#undef PROCESS_CHUNK
done:
        if (lane == 0) s_kc = kc;
    }
    __syncthreads();

    int kc = s_kc;
    const float4* bx = g_boxes + b * PRE_NMS;
    float4* o = (float4*)(out + (size_t)b * PROP * 4);
    if (kc >= PROP) {
        for (int r = threadIdx.x; r < PROP; r += blockDim.x) o[r] = bx[list[r]];
        return;
    }

    // fallback: exact direct sequential NMS over all 6000 boxes (rarely taken)
    __shared__ float4 kept[PROP];
    __shared__ float keptA7[PROP];
    int kk = 0;
    for (int i = 0; i < PRE_NMS && kk < PROP; ++i) {
        float4 bi = bx[i];
        float aR7 = 0.7f * ((bi.z - bi.x) * (bi.w - bi.y));
        int sup = 0;
        for (int j = threadIdx.x; j < kk; j += blockDim.x)
            if (iou_gt(bi, aR7, kept[j], keptA7[j])) sup = 1;
        sup = __syncthreads_or(sup);
        if (!sup) {
            if (threadIdx.x == 0) {
                kept[kk] = bi;
                keptA7[kk] = 0.7f * ((bi.z - bi.x) * (bi.w - bi.y) + 1e-8f);
            }
            kk++;
            __syncthreads();
        }
    }
    for (int r = threadIdx.x; r < PROP; r += blockDim.x) {
        float4 v = make_float4(0.f, 0.f, 0.f, 0.f);
        if (r < kk) v = kept[r];
        o[r] = v;
    }
}

// ---------------- launch ----------------
extern "C" void kernel_launch(void* const* d_in, const int* in_sizes, int n_in,
                              void* d_out, int out_size) {
    (void)in_sizes; (void)n_in; (void)out_size;
    const float4* cls4 = (const float4*)d_in[0];
    const float* rpn_bbox = (const float*)d_in[1];
    const float* anchors = (const float*)d_in[2];
    float* out = (float*)d_out;

    histscatter_kernel<<<HS_BLOCKS, HS_THREADS>>>(cls4);
    {
        dim3 grid(SB_GRID, BATCH);
        sortbox_kernel<<<grid, 128>>>(rpn_bbox, anchors);
    }
    {
        dim3 grid(NW2, PRE2 / 128, BATCH);   // (24, 12, 2)
        maskpre_kernel<<<grid, 128>>>();
    }
    nms_kernel<<<BATCH + 8, 256>>>(out);
}

// round 9
// speedup vs baseline: 1.3602x; 1.1455x over previous
#include <cuda_runtime.h>
#include <cuda_bf16.h>
#include <cstdint>

#define BATCH 2
#define NANCH 261888
#define PRE_NMS 6000
#define PRE2 1280          // prefix length for fast-path NMS
#define NW2 (PRE2 / 64)    // 20 words per prefix row
#define PROP 1000
#define NMS_THR 0.7f
#define NBINS 2048
#define SCAP 12288
#define BUCKET_CAP 2048
#define SB_GRID 128        // sortbox cutbin-relative grid width

#define HS_BLOCKS 64
#define HS_THREADS 1024
#define HS_PER_THREAD 4    // float4s per thread: 64*1024*4 = 262144 >= 261888

#define SMEM_NMS (PRE2 * NW2 * 8)   // 204800 B staged mask

typedef unsigned long long u64;

// ---------------- scratch (zero at module load; re-zeroed by tail kernel) -------
__device__ int g_hist[BATCH * NBINS];
__device__ int g_offset[BATCH * NBINS];
__device__ int g_binfill[BATCH * NBINS];
__device__ int g_cutbin[BATCH];
__device__ unsigned int g_ticket;
__device__ int g_ready;
__device__ u64 g_sorted[BATCH * SCAP];
__device__ float4 g_boxes[BATCH * PRE_NMS];
__device__ u64 g_mask2[(size_t)BATCH * PRE2 * NW2];   // 400 KB prefix mask

// ---------------- helpers ----------------
__device__ __forceinline__ int score_bin(float s) {
    int b = (int)(s * (float)NBINS);
    if (b < 0) b = 0;
    if (b > NBINS - 1) b = NBINS - 1;
    return b;
}

// keep ⟺ iou > THR ⟺ (1+THR)*inter > THR*(areaR+areaC+eps)  (denominator > 0)
__device__ __forceinline__ bool iou_gt(float4 a, float aR7, float4 c, float cA7) {
    float ih = fmaxf(fminf(a.z, c.z) - fmaxf(a.x, c.x), 0.f);
    float iw = fmaxf(fminf(a.w, c.w) - fmaxf(a.y, c.y), 0.f);
    float inter = ih * iw;
    return 1.7f * inter > aR7 + cA7;
}

// ------ 1: fused histogram + suffix-scan + scatter (single read of cls) --------
__global__ void __launch_bounds__(HS_THREADS, 1)
histscatter_kernel(const float4* __restrict__ cls4) {
    __shared__ int h[BATCH * NBINS];   // 16 KB
    for (int t = threadIdx.x; t < BATCH * NBINS; t += HS_THREADS) h[t] = 0;
    __syncthreads();
    const int total4 = BATCH * NANCH / 2;   // 261888
    const int half = NANCH / 2;
    const int gsz = HS_BLOCKS * HS_THREADS; // 65536
    int tid = blockIdx.x * HS_THREADS + threadIdx.x;

    float sc[HS_PER_THREAD * 2];
#pragma unroll
    for (int u = 0; u < HS_PER_THREAD; ++u) {
        int t = tid + u * gsz;
        float y = -1.f, w = -1.f;
        if (t < total4) {
            float4 v = cls4[t];
            y = v.y; w = v.w;
            int b = t / half;
            atomicAdd(&h[b * NBINS + score_bin(y)], 1);
            atomicAdd(&h[b * NBINS + score_bin(w)], 1);
        }
        sc[u * 2 + 0] = y;
        sc[u * 2 + 1] = w;
    }
    __syncthreads();
    for (int t = threadIdx.x; t < BATCH * NBINS; t += HS_THREADS)
        if (h[t]) atomicAdd(&g_hist[t], h[t]);

    __threadfence();
    __shared__ int is_last;
    if (threadIdx.x == 0)
        is_last = (atomicAdd(&g_ticket, 1u) == HS_BLOCKS - 1) ? 1 : 0;
    __syncthreads();

    if (is_last) {
        __shared__ int sA[1024], sB[1024];
        for (int b = 0; b < BATCH; ++b) {
            int t = threadIdx.x;
            int base = b * NBINS + t * 2;
            int h0 = g_hist[base + 0], h1 = g_hist[base + 1];
            int sum = h0 + h1;
            sA[t] = sum;
            __syncthreads();
            int* src = sA; int* dst = sB;
            for (int d = 1; d < 1024; d <<= 1) {
                int v = src[t];
                if (t + d < 1024) v += src[t + d];
                dst[t] = v;
                __syncthreads();
                int* tmp = src; src = dst; dst = tmp;
            }
            int excl = src[t] - sum;
            int off1 = excl;
            int off0 = off1 + h1;
            g_offset[base + 0] = off0; g_offset[base + 1] = off1;
            if (off1 + h1 >= PRE_NMS) atomicMax(&g_cutbin[b], t * 2 + 1);
            else if (off0 + h0 >= PRE_NMS) atomicMax(&g_cutbin[b], t * 2 + 0);
            __syncthreads();
        }
        __threadfence();
        if (threadIdx.x == 0) atomicExch(&g_ready, 1);
    }

    if (threadIdx.x == 0) {
        while (atomicAdd(&g_ready, 0) == 0) __nanosleep(128);
    }
    __syncthreads();
    __threadfence();

    int cut0 = g_cutbin[0];
    int cut1 = g_cutbin[1];
#pragma unroll
    for (int u = 0; u < HS_PER_THREAD; ++u) {
        int t = tid + u * gsz;
        if (t >= total4) continue;
        int b = t / half;
        int i0 = (t - b * half) * 2;
        int cut = (b == 0) ? cut0 : cut1;
#pragma unroll
        for (int e = 0; e < 2; ++e) {
            float s = sc[u * 2 + e];
            int i = i0 + e;
            int q = score_bin(s);
            if (q >= cut) {
                int pos = g_offset[b * NBINS + q] + atomicAdd(&g_binfill[b * NBINS + q], 1);
                if (pos < SCAP) {
                    unsigned int sb = __float_as_uint(s);
                    g_sorted[b * SCAP + pos] =
                        ((u64)sb << 32) | (u64)(0xFFFFFFFFu - (unsigned)i);
                }
            }
        }
    }
}

// ---------------- 2: per-bucket sort + box decode (cutbin-relative grid) -------
__global__ void sortbox_kernel(const float* __restrict__ rpn_bbox,
                               const float* __restrict__ anchors) {
    int b = blockIdx.y;
    int cut = g_cutbin[b];
    __shared__ u64 s[BUCKET_CAP];
    for (int bin = cut + blockIdx.x; bin < NBINS; bin += SB_GRID) {
        int cnt = g_hist[b * NBINS + bin];
        if (cnt <= 0) continue;
        if (cnt > BUCKET_CAP) cnt = BUCKET_CAP;
        int off = g_offset[b * NBINS + bin];
        if (off >= PRE_NMS) continue;
        int P = 1;
        while (P < cnt) P <<= 1;
        const u64* src = g_sorted + (size_t)b * SCAP + off;
        for (int t = threadIdx.x; t < P; t += blockDim.x)
            s[t] = (t < cnt) ? src[t] : 0ULL;
        __syncthreads();
        if (cnt > 1) {
            for (int k = 2; k <= P; k <<= 1) {
                for (int j = k >> 1; j > 0; j >>= 1) {
                    for (int i = threadIdx.x; i < P; i += blockDim.x) {
                        int ixj = i ^ j;
                        if (ixj > i) {
                            bool dir = ((i & k) == 0);
                            u64 a = s[i], c = s[ixj];
                            if ((a < c) == dir) { s[i] = c; s[ixj] = a; }
                        }
                    }
                    __syncthreads();
                }
            }
        }
        for (int t = threadIdx.x; t < cnt; t += blockDim.x) {
            int rank = off + t;
            if (rank >= PRE_NMS) continue;
            unsigned int low = (unsigned int)(s[t] & 0xFFFFFFFFu);
            int idx = (int)(0xFFFFFFFFu - low);
            size_t base = ((size_t)b * NANCH + (size_t)idx) * 4;
            float a0 = anchors[base + 0], a1 = anchors[base + 1];
            float a2 = anchors[base + 2], a3 = anchors[base + 3];
            float d0 = rpn_bbox[base + 0] * 0.1f;
            float d1 = rpn_bbox[base + 1] * 0.1f;
            float d2 = rpn_bbox[base + 2] * 0.2f;
            float d3 = rpn_bbox[base + 3] * 0.2f;
            float h = a2 - a0, w = a3 - a1;
            float cy = a0 + 0.5f * h + d0 * h;
            float cx = a1 + 0.5f * w + d1 * w;
            h = h * expf(d2);
            w = w * expf(d3);
            float y1 = cy - 0.5f * h;
            float x1 = cx - 0.5f * w;
            float y2 = y1 + h;
            float x2 = x1 + w;
            y1 = fminf(fmaxf(y1, 0.f), 1.f);
            x1 = fminf(fmaxf(x1, 0.f), 1.f);
            y2 = fminf(fmaxf(y2, 0.f), 1.f);
            x2 = fminf(fmaxf(x2, 0.f), 1.f);
            g_boxes[b * PRE_NMS + rank] = make_float4(y1, x1, y2, x2);
        }
        __syncthreads();
    }
}

// ---------------- 3: prefix IoU bitmask (upper triangle, no division) ----------
__global__ void __launch_bounds__(128) maskpre_kernel() {
    int b = blockIdx.z;
    int row0 = blockIdx.y * 128;
    int col0 = blockIdx.x * 64;
    if (col0 + 63 <= row0) return;   // sub-diagonal: never read
    __shared__ float4 cbox[64];
    __shared__ float cA7[64];
    int t = threadIdx.x;             // 128 threads
    if (t < 64) {
        float4 cb = g_boxes[b * PRE_NMS + col0 + t];
        cbox[t] = cb;
        cA7[t] = 0.7f * ((cb.z - cb.x) * (cb.w - cb.y) + 1e-8f);
    }
    __syncthreads();
    int r = row0 + t;
    float4 rb = g_boxes[b * PRE_NMS + r];
    float aR7 = 0.7f * ((rb.z - rb.x) * (rb.w - rb.y));
    unsigned lo = 0, hi = 0;
#pragma unroll
    for (int jj = 0; jj < 32; ++jj)
        if (iou_gt(rb, aR7, cbox[jj], cA7[jj])) lo |= (1u << jj);
#pragma unroll
    for (int jj = 0; jj < 32; ++jj)
        if (iou_gt(rb, aR7, cbox[32 + jj], cA7[32 + jj])) hi |= (1u << jj);
    g_mask2[((size_t)b * PRE2 + r) * NW2 + blockIdx.x] = ((u64)hi << 32) | lo;
}

// ------- 4: NMS — smem-staged mask, 32-row speculate/verify chunks -------------
__global__ void nms_kernel(float* __restrict__ out) {
    if (blockIdx.x >= BATCH) {
        // cleanup blocks: re-zero scratch for the next graph replay
        int start = (blockIdx.x - BATCH) * blockDim.x + threadIdx.x;
        for (int t = start; t < BATCH * NBINS; t += 8 * blockDim.x) {
            g_hist[t] = 0;
            g_binfill[t] = 0;
        }
        if (start == 0) {
            g_cutbin[0] = 0; g_cutbin[1] = 0;
            g_ticket = 0u;
            g_ready = 0;
        }
        return;
    }
    int b = blockIdx.x;
    extern __shared__ unsigned char dynsm[];
    u64* sm64 = (u64*)dynsm;
    __shared__ int list[PROP];
    __shared__ int s_kc;

    // stage the whole prefix mask into smem (all 8 warps, uint4 loads)
    {
        const uint4* src = (const uint4*)(g_mask2 + (size_t)b * PRE2 * NW2);
        uint4* dst = (uint4*)sm64;
        const int n16 = PRE2 * NW2 / 2;   // 12800
        for (int t = threadIdx.x; t < n16; t += blockDim.x) dst[t] = src[t];
    }
    __syncthreads();

    if (threadIdx.x < 32) {
        int lane = threadIdx.x;
        int ll = (lane < NW2) ? lane : 0;
        u64 rem = 0;
        int kc = 0;
        const int NCH = PRE2 / 32;   // 40 chunks of 32 rows
        for (int chunk = 0; chunk < NCH; ++chunk) {
            int base = chunk * 32;
            int w = base >> 6;
            int bp0 = base & 63;     // 0 or 32
            unsigned keptm = 0;
            if (lane == w) {
                // speculate: all rows not suppressed by pre-chunk state
                unsigned keptm0 = (unsigned)(~(rem >> bp0));
                // verify: any kept-kept suppression within the 32x32 diagonal?
                unsigned a0 = 0, a1 = 0, a2 = 0, a3 = 0;
#pragma unroll
                for (int k = 0; k < 32; k += 4) {
                    u64 r0 = sm64[(size_t)(base + k + 0) * NW2 + w];
                    u64 r1 = sm64[(size_t)(base + k + 1) * NW2 + w];
                    u64 r2 = sm64[(size_t)(base + k + 2) * NW2 + w];
                    u64 r3 = sm64[(size_t)(base + k + 3) * NW2 + w];
                    a0 |= (((unsigned)(r0 >> bp0)) & ~(1u << (k + 0))) & (0u - ((keptm0 >> (k + 0)) & 1u));
                    a1 |= (((unsigned)(r1 >> bp0)) & ~(1u << (k + 1))) & (0u - ((keptm0 >> (k + 1)) & 1u));
                    a2 |= (((unsigned)(r2 >> bp0)) & ~(1u << (k + 2))) & (0u - ((keptm0 >> (k + 2)) & 1u));
                    a3 |= (((unsigned)(r3 >> bp0)) & ~(1u << (k + 3))) & (0u - ((keptm0 >> (k + 3)) & 1u));
                }
                unsigned acc = (a0 | a1) | (a2 | a3);
                if ((acc & keptm0) == 0u) {
                    keptm = keptm0;   // speculation exact
                } else {
                    // rare: exact serial greedy within the chunk
                    unsigned rr = (unsigned)(rem >> bp0);
                    for (int k = 0; k < 32; ++k) {
                        if (!((rr >> k) & 1u)) {
                            keptm |= (1u << k);
                            u64 row = sm64[(size_t)(base + k) * NW2 + w];
                            rr |= (unsigned)(row >> bp0);
                        }
                    }
                }
            }
            keptm = __shfl_sync(0xffffffffu, keptm, w);
            // trim to first (PROP - kc) kept rows (later rows discarded anyway)
            int pc = __popc(keptm);
            int rema = PROP - kc;
            if (pc > rema) {
                while (pc > rema) {
                    keptm &= ~(1u << (31 - __clz(keptm)));
                    --pc;
                }
            }
            // masked OR of kept rows into rem (4-way ILP)
            {
                u64 o0 = 0, o1 = 0, o2 = 0, o3 = 0;
#pragma unroll
                for (int k = 0; k < 32; k += 4) {
                    o0 |= sm64[(size_t)(base + k + 0) * NW2 + ll] & (u64)(0ULL - (u64)((keptm >> (k + 0)) & 1u));
                    o1 |= sm64[(size_t)(base + k + 1) * NW2 + ll] & (u64)(0ULL - (u64)((keptm >> (k + 1)) & 1u));
                    o2 |= sm64[(size_t)(base + k + 2) * NW2 + ll] & (u64)(0ULL - (u64)((keptm >> (k + 2)) & 1u));
                    o3 |= sm64[(size_t)(base + k + 3) * NW2 + ll] & (u64)(0ULL - (u64)((keptm >> (k + 3)) & 1u));
                }
                rem |= (o0 | o1) | (o2 | o3);
            }
            if ((keptm >> lane) & 1u) {
                int pos = kc + __popc(keptm & ((1u << lane) - 1u));
                list[pos] = base + lane;
            }
            kc += pc;
            if (kc >= PROP) break;
        }
        if (lane == 0) s_kc = kc;
    }
    __syncthreads();

    int kc = s_kc;
    const float4* bx = g_boxes + b * PRE_NMS;
    float4* o = (float4*)(out + (size_t)b * PROP * 4);
    if (kc >= PROP) {
        for (int r = threadIdx.x; r < PROP; r += blockDim.x) o[r] = bx[list[r]];
        return;
    }

    // fallback: exact direct sequential NMS over all 6000 boxes (rarely taken)
    // kept arrays alias the dynamic smem (mask no longer needed)
    float4* kept = (float4*)dynsm;
    float* keptA7 = (float*)(dynsm + sizeof(float4) * PROP);
    int kk = 0;
    for (int i = 0; i < PRE_NMS && kk < PROP; ++i) {
        float4 bi = bx[i];
        float aR7 = 0.7f * ((bi.z - bi.x) * (bi.w - bi.y));
        int sup = 0;
        for (int j = threadIdx.x; j < kk; j += blockDim.x)
            if (iou_gt(bi, aR7, kept[j], keptA7[j])) sup = 1;
        sup = __syncthreads_or(sup);
        if (!sup) {
            if (threadIdx.x == 0) {
                kept[kk] = bi;
                keptA7[kk] = 0.7f * ((bi.z - bi.x) * (bi.w - bi.y) + 1e-8f);
            }
            kk++;
            __syncthreads();
        }
    }
    for (int r = threadIdx.x; r < PROP; r += blockDim.x) {
        float4 v = make_float4(0.f, 0.f, 0.f, 0.f);
        if (r < kk) v = kept[r];
        o[r] = v;
    }
}

// ---------------- launch ----------------
extern "C" void kernel_launch(void* const* d_in, const int* in_sizes, int n_in,
                              void* d_out, int out_size) {
    (void)in_sizes; (void)n_in; (void)out_size;
    const float4* cls4 = (const float4*)d_in[0];
    const float* rpn_bbox = (const float*)d_in[1];
    const float* anchors = (const float*)d_in[2];
    float* out = (float*)d_out;

    cudaFuncSetAttribute(nms_kernel, cudaFuncAttributeMaxDynamicSharedMemorySize,
                         SMEM_NMS);

    histscatter_kernel<<<HS_BLOCKS, HS_THREADS>>>(cls4);
    {
        dim3 grid(SB_GRID, BATCH);
        sortbox_kernel<<<grid, 128>>>(rpn_bbox, anchors);
    }
    {
        dim3 grid(NW2, PRE2 / 128, BATCH);   // (20, 10, 2)
        maskpre_kernel<<<grid, 128>>>();
    }
    nms_kernel<<<BATCH + 8, 256, SMEM_NMS>>>(out);
}

// round 10
// speedup vs baseline: 1.5354x; 1.1289x over previous
#include <cuda_runtime.h>
#include <cuda_bf16.h>
#include <cstdint>

#define BATCH 2
#define NANCH 261888
#define PRE_NMS 6000
#define PRE2 1280          // prefix length for fast-path NMS
#define NW2 (PRE2 / 64)    // 20 words per prefix row
#define NW2P 21            // padded smem row stride (bank-conflict break)
#define PROP 1000
#define NMS_THR 0.7f
#define NBINS 2048
#define SCAP 12288
#define BUCKET_CAP 2048
#define SB_GRID 128

#define HS_BLOCKS 64
#define HS_THREADS 1024
#define HS_PER_THREAD 4    // float4s per thread: 64*1024*4 = 262144 >= 261888

#define SMEM_NMS (PRE2 * NW2P * 8)   // 215040 B staged mask (padded)

typedef unsigned long long u64;

// ---------------- scratch (zero at module load; re-zeroed by tail kernel) -------
__device__ int g_hist[BATCH * NBINS];
__device__ int g_offset[BATCH * NBINS];
__device__ int g_binfill[BATCH * NBINS];
__device__ int g_cutbin[BATCH];
__device__ unsigned int g_ticket;
__device__ int g_ready;
__device__ u64 g_sorted[BATCH * SCAP];
__device__ float4 g_boxes[BATCH * PRE_NMS];
__device__ u64 g_mask2[(size_t)BATCH * PRE2 * NW2];   // 400 KB prefix mask

// ---------------- helpers ----------------
__device__ __forceinline__ int score_bin(float s) {
    int b = (int)(s * (float)NBINS);
    if (b < 0) b = 0;
    if (b > NBINS - 1) b = NBINS - 1;
    return b;
}

// keep ⟺ iou > THR ⟺ (1+THR)*inter > THR*(areaR+areaC+eps)  (denominator > 0)
__device__ __forceinline__ bool iou_gt(float4 a, float aR7, float4 c, float cA7) {
    float ih = fmaxf(fminf(a.z, c.z) - fmaxf(a.x, c.x), 0.f);
    float iw = fmaxf(fminf(a.w, c.w) - fmaxf(a.y, c.y), 0.f);
    float inter = ih * iw;
    return 1.7f * inter > aR7 + cA7;
}

// ------ 1: fused histogram + suffix-scan + scatter (single read of cls) --------
__global__ void __launch_bounds__(HS_THREADS, 1)
histscatter_kernel(const float4* __restrict__ cls4) {
    __shared__ int h[BATCH * NBINS];   // 16 KB
    for (int t = threadIdx.x; t < BATCH * NBINS; t += HS_THREADS) h[t] = 0;
    __syncthreads();
    const int total4 = BATCH * NANCH / 2;   // 261888
    const int half = NANCH / 2;
    const int gsz = HS_BLOCKS * HS_THREADS; // 65536
    int tid = blockIdx.x * HS_THREADS + threadIdx.x;

    float sc[HS_PER_THREAD * 2];
#pragma unroll
    for (int u = 0; u < HS_PER_THREAD; ++u) {
        int t = tid + u * gsz;
        float y = -1.f, w = -1.f;
        if (t < total4) {
            float4 v = cls4[t];
            y = v.y; w = v.w;
            int b = t / half;
            atomicAdd(&h[b * NBINS + score_bin(y)], 1);
            atomicAdd(&h[b * NBINS + score_bin(w)], 1);
        }
        sc[u * 2 + 0] = y;
        sc[u * 2 + 1] = w;
    }
    __syncthreads();
    for (int t = threadIdx.x; t < BATCH * NBINS; t += HS_THREADS)
        if (h[t]) atomicAdd(&g_hist[t], h[t]);

    __threadfence();
    __shared__ int is_last;
    if (threadIdx.x == 0)
        is_last = (atomicAdd(&g_ticket, 1u) == HS_BLOCKS - 1) ? 1 : 0;
    __syncthreads();

    if (is_last) {
        __shared__ int sA[1024], sB[1024];
        for (int b = 0; b < BATCH; ++b) {
            int t = threadIdx.x;
            int base = b * NBINS + t * 2;
            int h0 = g_hist[base + 0], h1 = g_hist[base + 1];
            int sum = h0 + h1;
            sA[t] = sum;
            __syncthreads();
            int* src = sA; int* dst = sB;
            for (int d = 1; d < 1024; d <<= 1) {
                int v = src[t];
                if (t + d < 1024) v += src[t + d];
                dst[t] = v;
                __syncthreads();
                int* tmp = src; src = dst; dst = tmp;
            }
            int excl = src[t] - sum;
            int off1 = excl;
            int off0 = off1 + h1;
            g_offset[base + 0] = off0; g_offset[base + 1] = off1;
            if (off1 + h1 >= PRE_NMS) atomicMax(&g_cutbin[b], t * 2 + 1);
            else if (off0 + h0 >= PRE_NMS) atomicMax(&g_cutbin[b], t * 2 + 0);
            __syncthreads();
        }
        __threadfence();
        if (threadIdx.x == 0) atomicExch(&g_ready, 1);
    }

    if (threadIdx.x == 0) {
        while (atomicAdd(&g_ready, 0) == 0) __nanosleep(128);
    }
    __syncthreads();
    __threadfence();

    int cut0 = g_cutbin[0];
    int cut1 = g_cutbin[1];
#pragma unroll
    for (int u = 0; u < HS_PER_THREAD; ++u) {
        int t = tid + u * gsz;
        if (t >= total4) continue;
        int b = t / half;
        int i0 = (t - b * half) * 2;
        int cut = (b == 0) ? cut0 : cut1;
#pragma unroll
        for (int e = 0; e < 2; ++e) {
            float s = sc[u * 2 + e];
            int i = i0 + e;
            int q = score_bin(s);
            if (q >= cut) {
                int pos = g_offset[b * NBINS + q] + atomicAdd(&g_binfill[b * NBINS + q], 1);
                if (pos < SCAP) {
                    unsigned int sb = __float_as_uint(s);
                    g_sorted[b * SCAP + pos] =
                        ((u64)sb << 32) | (u64)(0xFFFFFFFFu - (unsigned)i);
                }
            }
        }
    }
}

// ---------------- 2: per-bucket sort + box decode (cutbin-relative grid) -------
__global__ void sortbox_kernel(const float* __restrict__ rpn_bbox,
                               const float* __restrict__ anchors) {
    int b = blockIdx.y;
    int cut = g_cutbin[b];
    __shared__ u64 s[BUCKET_CAP];
    for (int bin = cut + blockIdx.x; bin < NBINS; bin += SB_GRID) {
        int cnt = g_hist[b * NBINS + bin];
        if (cnt <= 0) continue;
        if (cnt > BUCKET_CAP) cnt = BUCKET_CAP;
        int off = g_offset[b * NBINS + bin];
        if (off >= PRE_NMS) continue;
        int P = 1;
        while (P < cnt) P <<= 1;
        const u64* src = g_sorted + (size_t)b * SCAP + off;
        for (int t = threadIdx.x; t < P; t += blockDim.x)
            s[t] = (t < cnt) ? src[t] : 0ULL;
        __syncthreads();
        if (cnt > 1) {
            for (int k = 2; k <= P; k <<= 1) {
                for (int j = k >> 1; j > 0; j >>= 1) {
                    for (int i = threadIdx.x; i < P; i += blockDim.x) {
                        int ixj = i ^ j;
                        if (ixj > i) {
                            bool dir = ((i & k) == 0);
                            u64 a = s[i], c = s[ixj];
                            if ((a < c) == dir) { s[i] = c; s[ixj] = a; }
                        }
                    }
                    __syncthreads();
                }
            }
        }
        for (int t = threadIdx.x; t < cnt; t += blockDim.x) {
            int rank = off + t;
            if (rank >= PRE_NMS) continue;
            unsigned int low = (unsigned int)(s[t] & 0xFFFFFFFFu);
            int idx = (int)(0xFFFFFFFFu - low);
            size_t base = ((size_t)b * NANCH + (size_t)idx) * 4;
            float a0 = anchors[base + 0], a1 = anchors[base + 1];
            float a2 = anchors[base + 2], a3 = anchors[base + 3];
            float d0 = rpn_bbox[base + 0] * 0.1f;
            float d1 = rpn_bbox[base + 1] * 0.1f;
            float d2 = rpn_bbox[base + 2] * 0.2f;
            float d3 = rpn_bbox[base + 3] * 0.2f;
            float h = a2 - a0, w = a3 - a1;
            float cy = a0 + 0.5f * h + d0 * h;
            float cx = a1 + 0.5f * w + d1 * w;
            h = h * expf(d2);
            w = w * expf(d3);
            float y1 = cy - 0.5f * h;
            float x1 = cx - 0.5f * w;
            float y2 = y1 + h;
            float x2 = x1 + w;
            y1 = fminf(fmaxf(y1, 0.f), 1.f);
            x1 = fminf(fmaxf(x1, 0.f), 1.f);
            y2 = fminf(fmaxf(y2, 0.f), 1.f);
            x2 = fminf(fmaxf(x2, 0.f), 1.f);
            g_boxes[b * PRE_NMS + rank] = make_float4(y1, x1, y2, x2);
        }
        __syncthreads();
    }
}

// -------- 3: prefix IoU bitmask (LOWER triangle: row i needs cols < i) ---------
__global__ void __launch_bounds__(128) maskpre_kernel() {
    int b = blockIdx.z;
    int row0 = blockIdx.y * 128;
    int col0 = blockIdx.x * 64;
    if (col0 >= row0 + 128) return;   // no column < any row in block: never read
    __shared__ float4 cbox[64];
    __shared__ float cA7[64];
    int t = threadIdx.x;              // 128 threads
    if (t < 64) {
        float4 cb = g_boxes[b * PRE_NMS + col0 + t];
        cbox[t] = cb;
        cA7[t] = 0.7f * ((cb.z - cb.x) * (cb.w - cb.y) + 1e-8f);
    }
    __syncthreads();
    int r = row0 + t;
    float4 rb = g_boxes[b * PRE_NMS + r];
    float aR7 = 0.7f * ((rb.z - rb.x) * (rb.w - rb.y));
    unsigned lo = 0, hi = 0;
#pragma unroll
    for (int jj = 0; jj < 32; ++jj)
        if (iou_gt(rb, aR7, cbox[jj], cA7[jj])) lo |= (1u << jj);
#pragma unroll
    for (int jj = 0; jj < 32; ++jj)
        if (iou_gt(rb, aR7, cbox[32 + jj], cA7[32 + jj])) hi |= (1u << jj);
    g_mask2[((size_t)b * PRE2 + r) * NW2 + blockIdx.x] = ((u64)hi << 32) | lo;
}

// -------- 4: NMS — parallel Jacobi fixpoint (exact greedy) + fallback ----------
__global__ void nms_kernel(float* __restrict__ out) {
    if (blockIdx.x >= BATCH) {
        // cleanup blocks: re-zero scratch for the next graph replay
        int start = (blockIdx.x - BATCH) * blockDim.x + threadIdx.x;
        for (int t = start; t < BATCH * NBINS; t += 8 * blockDim.x) {
            g_hist[t] = 0;
            g_binfill[t] = 0;
        }
        if (start == 0) {
            g_cutbin[0] = 0; g_cutbin[1] = 0;
            g_ticket = 0u;
            g_ready = 0;
        }
        return;
    }
    int b = blockIdx.x;
    extern __shared__ unsigned char dynsm[];
    u64* sm64 = (u64*)dynsm;                     // [PRE2][NW2P]
    __shared__ int list[PROP];
    __shared__ u64 keptW[NW2];
    __shared__ unsigned char flags[PRE2];
    __shared__ int wpfx[NW2 + 1];
    __shared__ int s_changed, s_kc;

    // stage mask rows into padded smem (all 8 warps)
    {
        const u64* src = g_mask2 + (size_t)b * PRE2 * NW2;
        for (int idx = threadIdx.x; idx < PRE2 * NW2; idx += blockDim.x) {
            int row = idx / NW2;
            int w = idx - row * NW2;
            sm64[row * NW2P + w] = src[idx];
        }
    }
    for (int i = threadIdx.x; i < PRE2; i += blockDim.x) flags[i] = 1;
    if (threadIdx.x < NW2) keptW[threadIdx.x] = ~0ULL;
    __syncthreads();

    // Jacobi fixpoint: kept[i] = no earlier kept row suppresses i.
    // Unique fixpoint == greedy NMS (values determined by induction on i).
    for (int iter = 0; iter <= PRE2; ++iter) {
        if (threadIdx.x == 0) s_changed = 0;
        __syncthreads();
        for (int i = threadIdx.x; i < PRE2; i += blockDim.x) {
            const u64* row = sm64 + (size_t)i * NW2P;
            int wi = i >> 6;
            u64 sup = 0;
            for (int w = 0; w < wi; ++w) sup |= row[w] & keptW[w];
            u64 lm = (1ULL << (i & 63)) - 1ULL;   // bits j < i within word wi
            sup |= row[wi] & keptW[wi] & lm;
            unsigned char nk = (sup == 0) ? 1 : 0;
            if (nk != flags[i]) { flags[i] = nk; s_changed = 1; }
        }
        __syncthreads();
        if (!s_changed) break;
        if (threadIdx.x < NW2) {
            u64 wv = 0;
            int base = threadIdx.x * 64;
            for (int j = 0; j < 64; ++j) wv |= (u64)flags[base + j] << j;
            keptW[threadIdx.x] = wv;
        }
        __syncthreads();
    }

    // extract first PROP kept rows
    if (threadIdx.x == 0) {
        int acc = 0;
        for (int w = 0; w < NW2; ++w) { wpfx[w] = acc; acc += __popcll(keptW[w]); }
        s_kc = acc;
    }
    __syncthreads();
    int kc = s_kc;
    const float4* bx = g_boxes + b * PRE_NMS;
    float4* o = (float4*)(out + (size_t)b * PROP * 4);
    if (kc >= PROP) {
        for (int i = threadIdx.x; i < PRE2; i += blockDim.x) {
            if (flags[i]) {
                int wi = i >> 6;
                int pos = wpfx[wi] + __popcll(keptW[wi] & ((1ULL << (i & 63)) - 1ULL));
                if (pos < PROP) list[pos] = i;
            }
        }
        __syncthreads();
        for (int r = threadIdx.x; r < PROP; r += blockDim.x) o[r] = bx[list[r]];
        return;
    }

    // fallback: exact direct sequential NMS over all 6000 boxes (rarely taken)
    float4* kept = (float4*)dynsm;
    float* keptA7 = (float*)(dynsm + sizeof(float4) * PROP);
    __syncthreads();
    int kk = 0;
    for (int i = 0; i < PRE_NMS && kk < PROP; ++i) {
        float4 bi = bx[i];
        float aR7 = 0.7f * ((bi.z - bi.x) * (bi.w - bi.y));
        int sup = 0;
        for (int j = threadIdx.x; j < kk; j += blockDim.x)
            if (iou_gt(bi, aR7, kept[j], keptA7[j])) sup = 1;
        sup = __syncthreads_or(sup);
        if (!sup) {
            if (threadIdx.x == 0) {
                kept[kk] = bi;
                keptA7[kk] = 0.7f * ((bi.z - bi.x) * (bi.w - bi.y) + 1e-8f);
            }
            kk++;
            __syncthreads();
        }
    }
    for (int r = threadIdx.x; r < PROP; r += blockDim.x) {
        float4 v = make_float4(0.f, 0.f, 0.f, 0.f);
        if (r < kk) v = kept[r];
        o[r] = v;
    }
}

// ---------------- launch ----------------
extern "C" void kernel_launch(void* const* d_in, const int* in_sizes, int n_in,
                              void* d_out, int out_size) {
    (void)in_sizes; (void)n_in; (void)out_size;
    const float4* cls4 = (const float4*)d_in[0];
    const float* rpn_bbox = (const float*)d_in[1];
    const float* anchors = (const float*)d_in[2];
    float* out = (float*)d_out;

    cudaFuncSetAttribute(nms_kernel, cudaFuncAttributeMaxDynamicSharedMemorySize,
                         SMEM_NMS);

    histscatter_kernel<<<HS_BLOCKS, HS_THREADS>>>(cls4);
    {
        dim3 grid(SB_GRID, BATCH);
        sortbox_kernel<<<grid, 128>>>(rpn_bbox, anchors);
    }
    {
        dim3 grid(NW2, PRE2 / 128, BATCH);   // (20, 10, 2)
        maskpre_kernel<<<grid, 128>>>();
    }
    nms_kernel<<<BATCH + 8, 256, SMEM_NMS>>>(out);
}